// round 16
// baseline (speedup 1.0000x reference)
#include <cuda_runtime.h>
#include <cstdint>

// Upsample_72619307041391
// x: (32, 512, 512, 1) f32, kernel: (4,4) f32 -> out: (32, 1024, 1024, 1) f32
//
// out = conv1d_horiz( repeat2x2(x), kernel.flatten()[1x16], SAME(pad_left=7) )
// Collapsed: output row pairs (2r, 2r+1) identical; even output cols = 9-tap
// FIR on x (offsets -4..+4), odd cols = 8-tap FIR (offsets -3..+4).
//
// R16: direct 256-bit register stores (st.global.v8.b32, sm_100+), with L2
// residency hints (input evict_last / output evict_first). No SMEM, no TMA,
// no syncs: each thread computes 8 output floats and stores them twice
// (rows 2r, 2r+1) with exactly two v8 store instructions.

#define W_IN    512
#define W_OUT   1024
#define TPR     128          // threads per x-row (512/4)

__device__ __forceinline__ float4 ldg_resident(const float4* p, uint64_t pol) {
    float4 v;
    asm("ld.global.nc.L2::cache_hint.v4.f32 {%0,%1,%2,%3}, [%4], %5;"
        : "=f"(v.x), "=f"(v.y), "=f"(v.z), "=f"(v.w) : "l"(p), "l"(pol));
    return v;
}

__device__ __forceinline__ void stg_v8_stream(float* p, const float* v, uint64_t pol) {
    asm volatile(
        "st.global.L2::cache_hint.v8.b32 [%0], {%1,%2,%3,%4,%5,%6,%7,%8}, %9;"
        :: "l"(p),
           "r"(__float_as_uint(v[0])), "r"(__float_as_uint(v[1])),
           "r"(__float_as_uint(v[2])), "r"(__float_as_uint(v[3])),
           "r"(__float_as_uint(v[4])), "r"(__float_as_uint(v[5])),
           "r"(__float_as_uint(v[6])), "r"(__float_as_uint(v[7])),
           "l"(pol)
        : "memory");
}

__global__ __launch_bounds__(256, 8)
void upfir_kernel(const float* __restrict__ x,
                  const float* __restrict__ ker,
                  float* __restrict__ out)
{
    const int t    = threadIdx.x & (TPR - 1);     // 0..127 within row
    const int half = threadIdx.x >> 7;            // 0/1: which row of the pair
    const int row  = blockIdx.x * 2 + half;       // n*512 + r

    // L2 policies: inputs evict_last (keep resident), outputs evict_first.
    uint64_t pol_keep, pol_stream;
    asm("createpolicy.fractional.L2::evict_last.b64 %0, 1.0;"  : "=l"(pol_keep));
    asm("createpolicy.fractional.L2::evict_first.b64 %0, 1.0;" : "=l"(pol_stream));

    // FIR taps: 16 contiguous floats -> 4 vector loads (uniform broadcast).
    const float4* k4 = reinterpret_cast<const float4*>(ker);
    const float4 ka = ldg_resident(k4 + 0, pol_keep);
    const float4 kb = ldg_resident(k4 + 1, pol_keep);
    const float4 kc = ldg_resident(k4 + 2, pol_keep);
    const float4 kd = ldg_resident(k4 + 3, pol_keep);
    const float k[16] = { ka.x, ka.y, ka.z, ka.w,
                          kb.x, kb.y, kb.z, kb.w,
                          kc.x, kc.y, kc.z, kc.w,
                          kd.x, kd.y, kd.z, kd.w };

    // Combined phase weights.
    float se[9], so[8];
    se[0] = k[0];
    #pragma unroll
    for (int d = 1; d < 8; d++) se[d] = k[2*d - 1] + k[2*d];
    se[8] = k[15];
    #pragma unroll
    for (int d = 0; d < 8; d++) so[d] = k[2*d] + k[2*d + 1];

    // 12-value footprint: xs[i] = x[row, 4t + i - 4], zero outside [0,512)
    const float4* xr4 = reinterpret_cast<const float4*>(x + (size_t)row * W_IN);
    const float4 zero4 = make_float4(0.f, 0.f, 0.f, 0.f);
    float4 a = (t > 0)       ? ldg_resident(xr4 + (t - 1), pol_keep) : zero4;
    float4 b =                 ldg_resident(xr4 + t,       pol_keep);
    float4 c = (t < TPR - 1) ? ldg_resident(xr4 + (t + 1), pol_keep) : zero4;

    float xs[12] = { a.x, a.y, a.z, a.w,
                     b.x, b.y, b.z, b.w,
                     c.x, c.y, c.z, c.w };

    float e0=0.f, e1=0.f, e2=0.f, e3=0.f;
    float o0=0.f, o1=0.f, o2=0.f, o3=0.f;
    #pragma unroll
    for (int d = 0; d < 9; d++) {
        const float w = se[d];
        e0 = fmaf(w, xs[d    ], e0);
        e1 = fmaf(w, xs[d + 1], e1);
        e2 = fmaf(w, xs[d + 2], e2);
        e3 = fmaf(w, xs[d + 3], e3);
    }
    #pragma unroll
    for (int d = 0; d < 8; d++) {
        const float w = so[d];
        o0 = fmaf(w, xs[d + 1], o0);
        o1 = fmaf(w, xs[d + 2], o1);
        o2 = fmaf(w, xs[d + 3], o2);
        o3 = fmaf(w, xs[d + 4], o3);
    }

    // 8 contiguous output floats (cols 8t..8t+7), stored to both dup rows.
    const float v[8] = { e0, o0, e1, o1, e2, o2, e3, o3 };

    const int n = row >> 9;
    const int r = row & 511;
    float* o = out + ((size_t)n * 1024 + 2 * (size_t)r) * W_OUT + 8 * (size_t)t;

    stg_v8_stream(o,         v, pol_stream);   // row 2r
    stg_v8_stream(o + W_OUT, v, pol_stream);   // row 2r+1
}

extern "C" void kernel_launch(void* const* d_in, const int* in_sizes, int n_in,
                              void* d_out, int out_size)
{
    const float* x   = (const float*)d_in[0];   // 32*512*512
    const float* ker = (const float*)d_in[1];   // 16 floats (4x4 row-major)
    float* out = (float*)d_out;                 // 32*1024*1024

    dim3 grid(32 * 512 / 2);   // 8192 blocks, 2 input rows each
    dim3 block(256);
    upfir_kernel<<<grid, block>>>(x, ker, out);
}

// round 17
// speedup vs baseline: 1.1689x; 1.1689x over previous
#include <cuda_runtime.h>
#include <cstdint>

// Upsample_72619307041391
// x: (32, 512, 512, 1) f32, kernel: (4,4) f32 -> out: (32, 1024, 1024, 1) f32
//
// out = conv1d_horiz( repeat2x2(x), kernel.flatten()[1x16], SAME(pad_left=7) )
// Collapsed: output row pairs (2r, 2r+1) identical; even output cols = 9-tap
// FIR on x (offsets -4..+4), odd cols = 8-tap FIR (offsets -3..+4).
//
// R17 = R10 (warp-autonomous 1KB TMA stores + L2 residency hints) with the
// CTA-exit wait relaxed to cp.async.bulk.wait_group.read: releases when TMA
// has READ the SMEM (sufficient for SMEM lifetime); global visibility is
// guaranteed by kernel-completion semantics. Removes the per-CTA L2-ack tail.

#define W_IN    512
#define W_OUT   1024
#define TPR     128          // threads per x-row (512/4)

__device__ __forceinline__ uint32_t smem_u32(const void* p) {
    uint32_t a;
    asm("{ .reg .u64 t; cvta.to.shared.u64 t, %1; cvt.u32.u64 %0, t; }"
        : "=r"(a) : "l"(p));
    return a;
}

__device__ __forceinline__ float4 ldg_resident(const float4* p, uint64_t pol) {
    float4 v;
    asm("ld.global.nc.L2::cache_hint.v4.f32 {%0,%1,%2,%3}, [%4], %5;"
        : "=f"(v.x), "=f"(v.y), "=f"(v.z), "=f"(v.w) : "l"(p), "l"(pol));
    return v;
}

__global__ __launch_bounds__(256, 8)
void upfir_kernel(const float* __restrict__ x,
                  const float* __restrict__ ker,
                  float* __restrict__ out)
{
    // One private 1KB (256-float) slice per warp.
    __shared__ __align__(16) float swarp[8][256];

    const int lane = threadIdx.x & 31;
    const int w    = threadIdx.x >> 5;            // warp 0..7
    const int t    = threadIdx.x & (TPR - 1);     // 0..127 within row
    const int half = threadIdx.x >> 7;            // 0/1: which row of the pair
    const int q    = w & 3;                       // quarter of the row
    const int row  = blockIdx.x * 2 + half;       // n*512 + r

    // L2 policies: inputs evict_last (keep resident), outputs evict_first.
    uint64_t pol_keep, pol_stream;
    asm("createpolicy.fractional.L2::evict_last.b64 %0, 1.0;"  : "=l"(pol_keep));
    asm("createpolicy.fractional.L2::evict_first.b64 %0, 1.0;" : "=l"(pol_stream));

    // FIR taps: 16 contiguous floats -> 4 vector loads (uniform broadcast).
    const float4* k4 = reinterpret_cast<const float4*>(ker);
    const float4 ka = ldg_resident(k4 + 0, pol_keep);
    const float4 kb = ldg_resident(k4 + 1, pol_keep);
    const float4 kc = ldg_resident(k4 + 2, pol_keep);
    const float4 kd = ldg_resident(k4 + 3, pol_keep);
    const float k[16] = { ka.x, ka.y, ka.z, ka.w,
                          kb.x, kb.y, kb.z, kb.w,
                          kc.x, kc.y, kc.z, kc.w,
                          kd.x, kd.y, kd.z, kd.w };

    // Combined phase weights.
    float se[9], so[8];
    se[0] = k[0];
    #pragma unroll
    for (int d = 1; d < 8; d++) se[d] = k[2*d - 1] + k[2*d];
    se[8] = k[15];
    #pragma unroll
    for (int d = 0; d < 8; d++) so[d] = k[2*d] + k[2*d + 1];

    // 12-value footprint: xs[i] = x[row, 4t + i - 4], zero outside [0,512)
    const float4* xr4 = reinterpret_cast<const float4*>(x + (size_t)row * W_IN);
    const float4 zero4 = make_float4(0.f, 0.f, 0.f, 0.f);
    float4 a = (t > 0)       ? ldg_resident(xr4 + (t - 1), pol_keep) : zero4;
    float4 b =                 ldg_resident(xr4 + t,       pol_keep);
    float4 c = (t < TPR - 1) ? ldg_resident(xr4 + (t + 1), pol_keep) : zero4;

    float xs[12] = { a.x, a.y, a.z, a.w,
                     b.x, b.y, b.z, b.w,
                     c.x, c.y, c.z, c.w };

    float e0=0.f, e1=0.f, e2=0.f, e3=0.f;
    float o0=0.f, o1=0.f, o2=0.f, o3=0.f;
    #pragma unroll
    for (int d = 0; d < 9; d++) {
        const float wgt = se[d];
        e0 = fmaf(wgt, xs[d    ], e0);
        e1 = fmaf(wgt, xs[d + 1], e1);
        e2 = fmaf(wgt, xs[d + 2], e2);
        e3 = fmaf(wgt, xs[d + 3], e3);
    }
    #pragma unroll
    for (int d = 0; d < 8; d++) {
        const float wgt = so[d];
        o0 = fmaf(wgt, xs[d + 1], o0);
        o1 = fmaf(wgt, xs[d + 2], o1);
        o2 = fmaf(wgt, xs[d + 3], o2);
        o3 = fmaf(wgt, xs[d + 4], o3);
    }

    // Stage this warp's contiguous 1KB chunk (out cols 256q .. 256q+255).
    float4* s = reinterpret_cast<float4*>(&swarp[w][8 * lane]);
    s[0] = make_float4(e0, o0, e1, o1);
    s[1] = make_float4(e2, o2, e3, o3);

    __syncwarp();

    // Lane 0 fires two 1KB bulk stores (rows 2r and 2r+1), evict_first policy.
    if (lane == 0) {
        asm volatile("fence.proxy.async.shared::cta;" ::: "memory");
        const int n = row >> 9;
        const int r = row & 511;
        float* dst = out + ((size_t)n * 1024 + 2 * (size_t)r) * W_OUT + 256 * (size_t)q;
        uint32_t src = smem_u32(&swarp[w][0]);
        asm volatile(
            "cp.async.bulk.global.shared::cta.bulk_group.L2::cache_hint"
            " [%0], [%1], %2, %3;"
            :: "l"(dst), "r"(src), "r"(256 * 4), "l"(pol_stream) : "memory");
        asm volatile(
            "cp.async.bulk.global.shared::cta.bulk_group.L2::cache_hint"
            " [%0], [%1], %2, %3;"
            :: "l"(dst + W_OUT), "r"(src), "r"(256 * 4), "l"(pol_stream) : "memory");
        asm volatile("cp.async.bulk.commit_group;" ::: "memory");
        // Only wait until TMA has READ the SMEM source (slice lifetime);
        // global write visibility is guaranteed at kernel completion.
        asm volatile("cp.async.bulk.wait_group.read 0;" ::: "memory");
    }
}

extern "C" void kernel_launch(void* const* d_in, const int* in_sizes, int n_in,
                              void* d_out, int out_size)
{
    const float* x   = (const float*)d_in[0];   // 32*512*512
    const float* ker = (const float*)d_in[1];   // 16 floats (4x4 row-major)
    float* out = (float*)d_out;                 // 32*1024*1024

    dim3 grid(32 * 512 / 2);   // 8192 blocks, 2 input rows each
    dim3 block(256);
    upfir_kernel<<<grid, block>>>(x, ker, out);
}